// round 1
// baseline (speedup 1.0000x reference)
#include <cuda_runtime.h>
#include <math.h>

#define NN     10000
#define EE     320000
#define NE     (EE + NN)     // with self loops
#define NFEAT  512
#define NHID1  256
#define NHID2  64
#define H1     128           // 2*NHID2
#define NEG_SLOPE 0.2f
#define BN_EPS 1e-5f
#define MAXDEG 512

// output layout (flattened tuple: emb, re_x, readj, mu, logvar)
#define EMB_OFF   ((size_t)0)
#define REX_OFF   ((size_t)NN * NHID2)                       // 640000
#define READJ_OFF (REX_OFF + (size_t)NN * NFEAT)             // 5760000
#define MU_OFF    (READJ_OFF + (size_t)NN * NN)              // 105760000
#define LV_OFF    (MU_OFF + (size_t)NN * NHID2)              // 106400000

// ---------------- scratch (device globals; no allocation allowed) ----------
__device__ float g_xl1[NN * H1];
__device__ float g_xr1[NN * H1];
__device__ float g_h  [NN * H1];
__device__ float g_xl2[NN * NHID2];
__device__ float g_xr2[NN * NHID2];
__device__ float g_xl3[NN * NHID2];
__device__ float g_xr3[NN * NHID2];
__device__ float g_d  [NN * NHID1];
__device__ int   g_deg[NN];
__device__ int   g_rowptr[NN + 1];
__device__ int   g_cursor[NN];
__device__ int   g_srclist[NE];
__device__ float g_mean[NHID1];
__device__ float g_rstd[NHID1];

// ---------------- CSR build ----------------
__global__ void k_zero_counts() {
    int i = blockIdx.x * blockDim.x + threadIdx.x;
    if (i < NN) { g_deg[i] = 0; g_cursor[i] = 0; }
}

__global__ void k_count_deg(const int* __restrict__ edge_index) {
    int i = blockIdx.x * blockDim.x + threadIdx.x;
    if (i >= NE) return;
    int tgt = (i < EE) ? edge_index[EE + i] : (i - EE);
    atomicAdd(&g_deg[tgt], 1);
}

__global__ void k_scan_deg() {
    __shared__ int s[1024];
    __shared__ int sc;
    int tid = threadIdx.x;
    if (tid == 0) { sc = 0; g_rowptr[0] = 0; }
    __syncthreads();
    for (int base = 0; base < NN; base += 1024) {
        int i = base + tid;
        s[tid] = (i < NN) ? g_deg[i] : 0;
        __syncthreads();
        for (int off = 1; off < 1024; off <<= 1) {
            int t = (tid >= off) ? s[tid - off] : 0;
            __syncthreads();
            s[tid] += t;
            __syncthreads();
        }
        int c = sc;
        if (i < NN) g_rowptr[i + 1] = c + s[tid];
        __syncthreads();
        if (tid == 0) sc = c + s[1023];
        __syncthreads();
    }
}

__global__ void k_fill_list(const int* __restrict__ edge_index) {
    int i = blockIdx.x * blockDim.x + threadIdx.x;
    if (i >= NE) return;
    int src, tgt;
    if (i < EE) { src = edge_index[i]; tgt = edge_index[EE + i]; }
    else        { src = i - EE;        tgt = i - EE; }
    int pos = atomicAdd(&g_cursor[tgt], 1);
    g_srclist[g_rowptr[tgt] + pos] = src;
}

// ---------------- tiled SGEMM: C[M,Nc] = A[M,K] @ B[K,Nc] + bias ----------
// 64x64 tile, BK=16, 256 threads (16x16), 4x4 per thread.
__global__ void sgemm_bias(const float* __restrict__ A, const float* __restrict__ B,
                           const float* __restrict__ bias, float* __restrict__ C,
                           int M, int K, int Nc) {
    __shared__ float As[16][65];
    __shared__ float Bs[16][65];
    int tx = threadIdx.x, ty = threadIdx.y;
    int tid = ty * 16 + tx;
    int row0 = blockIdx.y * 64, col0 = blockIdx.x * 64;
    float acc[4][4] = {};
    for (int k0 = 0; k0 < K; k0 += 16) {
#pragma unroll
        for (int i = 0; i < 4; i++) {
            int e = tid + i * 256;
            int k = e & 15, m = e >> 4;
            As[k][m] = (row0 + m < M) ? A[(size_t)(row0 + m) * K + k0 + k] : 0.f;
        }
#pragma unroll
        for (int i = 0; i < 4; i++) {
            int e = tid + i * 256;
            int n = e & 63, k = e >> 6;
            Bs[k][n] = B[(size_t)(k0 + k) * Nc + col0 + n];
        }
        __syncthreads();
#pragma unroll
        for (int kk = 0; kk < 16; kk++) {
            float a[4], b[4];
#pragma unroll
            for (int i = 0; i < 4; i++) a[i] = As[kk][ty * 4 + i];
#pragma unroll
            for (int j = 0; j < 4; j++) b[j] = Bs[kk][tx * 4 + j];
#pragma unroll
            for (int i = 0; i < 4; i++)
#pragma unroll
                for (int j = 0; j < 4; j++) acc[i][j] += a[i] * b[j];
        }
        __syncthreads();
    }
#pragma unroll
    for (int i = 0; i < 4; i++) {
        int r = row0 + ty * 4 + i;
        if (r < M) {
#pragma unroll
            for (int j = 0; j < 4; j++) {
                int c = col0 + tx * 4 + j;
                C[(size_t)r * Nc + c] = acc[i][j] + bias[c];
            }
        }
    }
}

// ---------------- GATv2 aggregation (one block per target node) -----------
template <int C>
__global__ void gat_agg(const float* __restrict__ xl, const float* __restrict__ xr,
                        const float* __restrict__ att, const float* __restrict__ bias,
                        float* __restrict__ out) {
    constexpr int W = C / 32;
    int t = blockIdx.x;
    int tid = threadIdx.x, lane = tid & 31, warp = tid >> 5;
    __shared__ float s_xr[C], s_att[C];
    __shared__ float s_e[MAXDEG];
    __shared__ int   s_src[MAXDEG];
    __shared__ float s_red[W];
    s_xr[tid]  = xr[(size_t)t * C + tid];
    s_att[tid] = att[tid];
    int beg = g_rowptr[t];
    int deg = g_rowptr[t + 1] - beg;
    __syncthreads();

    // pass A: per-warp edge scores e_j = a . leaky(xl[src] + xr[tgt])
    for (int j = warp; j < deg; j += W) {
        int src = g_srclist[beg + j];
        const float* xs = xl + (size_t)src * C;
        float p = 0.f;
#pragma unroll
        for (int k = 0; k < C / 32; k++) {
            int c = lane + 32 * k;
            float s = xs[c] + s_xr[c];
            s = fmaxf(s, NEG_SLOPE * s);
            p += s_att[c] * s;
        }
#pragma unroll
        for (int o = 16; o; o >>= 1) p += __shfl_xor_sync(0xffffffffu, p, o);
        if (lane == 0) { s_e[j] = p; s_src[j] = src; }
    }
    __syncthreads();

    // max over edges
    float m = -1e30f;
    for (int j = tid; j < deg; j += C) m = fmaxf(m, s_e[j]);
#pragma unroll
    for (int o = 16; o; o >>= 1) m = fmaxf(m, __shfl_xor_sync(0xffffffffu, m, o));
    if (lane == 0) s_red[warp] = m;
    __syncthreads();
    m = s_red[0];
#pragma unroll
    for (int w = 1; w < W; w++) m = fmaxf(m, s_red[w]);
    __syncthreads();

    // exp + sum
    float ssum = 0.f;
    for (int j = tid; j < deg; j += C) {
        float wj = __expf(s_e[j] - m);
        s_e[j] = wj;
        ssum += wj;
    }
#pragma unroll
    for (int o = 16; o; o >>= 1) ssum += __shfl_xor_sync(0xffffffffu, ssum, o);
    if (lane == 0) s_red[warp] = ssum;
    __syncthreads();
    ssum = 0.f;
#pragma unroll
    for (int w = 0; w < W; w++) ssum += s_red[w];
    float inv = 1.f / ssum;

    // pass B: weighted aggregation of xl[src]
    float acc = 0.f;
    for (int j = 0; j < deg; j++) {
        acc += s_e[j] * xl[(size_t)s_src[j] * C + tid];
    }
    out[(size_t)t * C + tid] = acc * inv + bias[tid];
}

// ---------------- batch norm ----------------
__global__ void bn_stats(const float* __restrict__ h, int C) {
    int c = blockIdx.x;
    int tid = threadIdx.x;
    float s = 0.f, s2 = 0.f;
    for (int r = tid; r < NN; r += 256) {
        float v = h[(size_t)r * C + c];
        s += v; s2 += v * v;
    }
    __shared__ float sh[8], sh2[8];
#pragma unroll
    for (int o = 16; o; o >>= 1) {
        s  += __shfl_xor_sync(0xffffffffu, s,  o);
        s2 += __shfl_xor_sync(0xffffffffu, s2, o);
    }
    if ((tid & 31) == 0) { sh[tid >> 5] = s; sh2[tid >> 5] = s2; }
    __syncthreads();
    if (tid == 0) {
        float ts = 0.f, ts2 = 0.f;
        for (int w = 0; w < 8; w++) { ts += sh[w]; ts2 += sh2[w]; }
        float mean = ts / NN;
        float var = ts2 / NN - mean * mean;
        g_mean[c] = mean;
        g_rstd[c] = rsqrtf(var + BN_EPS);
    }
}

__global__ void bn_apply_relu(float* __restrict__ buf, const float* __restrict__ g,
                              const float* __restrict__ b, int C, int total) {
    int i = blockIdx.x * blockDim.x + threadIdx.x;
    if (i >= total) return;
    int c = i % C;
    float v = (buf[i] - g_mean[c]) * g_rstd[c] * g[c] + b[c];
    buf[i] = fmaxf(v, 0.f);
}

// ---------------- reparameterize ----------------
__global__ void k_reparam(const float* __restrict__ eps, float* __restrict__ out) {
    int i = blockIdx.x * blockDim.x + threadIdx.x;
    if (i >= NN * NHID2) return;
    float mu = out[MU_OFF + i];
    float lv = out[LV_OFF + i];
    out[EMB_OFF + i] = eps[i] * __expf(lv) + mu;
}

// ---------------- readj = sigmoid(emb @ emb^T) ----------------
__global__ void gram_sigmoid(const float* __restrict__ E, float* __restrict__ out) {
    __shared__ float Ea[64][65];
    __shared__ float Eb[64][65];
    int tx = threadIdx.x, ty = threadIdx.y;
    int tid = ty * 16 + tx;
    int row0 = blockIdx.y * 64, col0 = blockIdx.x * 64;
#pragma unroll
    for (int i = 0; i < 16; i++) {
        int e = tid + i * 256;
        int k = e & 63, m = e >> 6;
        Ea[k][m] = (row0 + m < NN) ? E[(size_t)(row0 + m) * 64 + k] : 0.f;
        Eb[k][m] = (col0 + m < NN) ? E[(size_t)(col0 + m) * 64 + k] : 0.f;
    }
    __syncthreads();
    float acc[4][4] = {};
#pragma unroll 16
    for (int kk = 0; kk < 64; kk++) {
        float a[4], b[4];
#pragma unroll
        for (int i = 0; i < 4; i++) a[i] = Ea[kk][ty * 4 + i];
#pragma unroll
        for (int j = 0; j < 4; j++) b[j] = Eb[kk][tx * 4 + j];
#pragma unroll
        for (int i = 0; i < 4; i++)
#pragma unroll
            for (int j = 0; j < 4; j++) acc[i][j] += a[i] * b[j];
    }
#pragma unroll
    for (int i = 0; i < 4; i++) {
        int r = row0 + ty * 4 + i;
        if (r < NN) {
#pragma unroll
            for (int j = 0; j < 4; j++) {
                int c = col0 + tx * 4 + j;
                if (c < NN) out[(size_t)r * NN + c] = 1.f / (1.f + __expf(-acc[i][j]));
            }
        }
    }
}

// ---------------- launch ----------------
extern "C" void kernel_launch(void* const* d_in, const int* in_sizes, int n_in,
                              void* d_out, int out_size) {
    const float* x   = (const float*)d_in[0];
    const int*   ei  = (const int*)  d_in[1];
    const float* eps = (const float*)d_in[2];
    const float* w1l = (const float*)d_in[3];
    const float* b1l = (const float*)d_in[4];
    const float* w1r = (const float*)d_in[5];
    const float* b1r = (const float*)d_in[6];
    const float* a1  = (const float*)d_in[7];
    const float* bias1 = (const float*)d_in[8];
    const float* bn1_g = (const float*)d_in[9];
    const float* bn1_b = (const float*)d_in[10];
    const float* w2l = (const float*)d_in[11];
    const float* b2l = (const float*)d_in[12];
    const float* w2r = (const float*)d_in[13];
    const float* b2r = (const float*)d_in[14];
    const float* a2  = (const float*)d_in[15];
    const float* bias2 = (const float*)d_in[16];
    const float* w3l = (const float*)d_in[17];
    const float* b3l = (const float*)d_in[18];
    const float* w3r = (const float*)d_in[19];
    const float* b3r = (const float*)d_in[20];
    const float* a3  = (const float*)d_in[21];
    const float* bias3 = (const float*)d_in[22];
    const float* dw1 = (const float*)d_in[23];
    const float* db1 = (const float*)d_in[24];
    const float* dbn_g = (const float*)d_in[25];
    const float* dbn_b = (const float*)d_in[26];
    const float* dw2 = (const float*)d_in[27];
    const float* db2 = (const float*)d_in[28];
    float* out = (float*)d_out;

    // resolve scratch symbol addresses
    float *p_xl1, *p_xr1, *p_h, *p_xl2, *p_xr2, *p_xl3, *p_xr3, *p_d;
    cudaGetSymbolAddress((void**)&p_xl1, g_xl1);
    cudaGetSymbolAddress((void**)&p_xr1, g_xr1);
    cudaGetSymbolAddress((void**)&p_h,   g_h);
    cudaGetSymbolAddress((void**)&p_xl2, g_xl2);
    cudaGetSymbolAddress((void**)&p_xr2, g_xr2);
    cudaGetSymbolAddress((void**)&p_xl3, g_xl3);
    cudaGetSymbolAddress((void**)&p_xr3, g_xr3);
    cudaGetSymbolAddress((void**)&p_d,   g_d);

    dim3 blk16(16, 16);

    // ---- CSR build (edges + self loops, grouped by target) ----
    k_zero_counts<<<(NN + 255) / 256, 256>>>();
    k_count_deg<<<(NE + 255) / 256, 256>>>(ei);
    k_scan_deg<<<1, 1024>>>();
    k_fill_list<<<(NE + 255) / 256, 256>>>(ei);

    // ---- layer 1 linear transforms ----
    sgemm_bias<<<dim3(H1 / 64, (NN + 63) / 64), blk16>>>(x, w1l, b1l, p_xl1, NN, NFEAT, H1);
    sgemm_bias<<<dim3(H1 / 64, (NN + 63) / 64), blk16>>>(x, w1r, b1r, p_xr1, NN, NFEAT, H1);

    // ---- GAT layer 1 -> BN -> ReLU ----
    gat_agg<H1><<<NN, H1>>>(p_xl1, p_xr1, a1, bias1, p_h);
    bn_stats<<<H1, 256>>>(p_h, H1);
    bn_apply_relu<<<(NN * H1 + 255) / 256, 256>>>(p_h, bn1_g, bn1_b, H1, NN * H1);

    // ---- layers 2 & 3 linear transforms ----
    sgemm_bias<<<dim3(NHID2 / 64, (NN + 63) / 64), blk16>>>(p_h, w2l, b2l, p_xl2, NN, H1, NHID2);
    sgemm_bias<<<dim3(NHID2 / 64, (NN + 63) / 64), blk16>>>(p_h, w2r, b2r, p_xr2, NN, H1, NHID2);
    sgemm_bias<<<dim3(NHID2 / 64, (NN + 63) / 64), blk16>>>(p_h, w3l, b3l, p_xl3, NN, H1, NHID2);
    sgemm_bias<<<dim3(NHID2 / 64, (NN + 63) / 64), blk16>>>(p_h, w3r, b3r, p_xr3, NN, H1, NHID2);

    // ---- GAT layers 2 (mu) and 3 (logvar) straight into output ----
    gat_agg<NHID2><<<NN, NHID2>>>(p_xl2, p_xr2, a2, bias2, out + MU_OFF);
    gat_agg<NHID2><<<NN, NHID2>>>(p_xl3, p_xr3, a3, bias3, out + LV_OFF);

    // ---- reparameterize: emb = eps*exp(logvar)+mu ----
    k_reparam<<<(NN * NHID2 + 255) / 256, 256>>>(eps, out);

    // ---- readj = sigmoid(emb @ emb^T) ----
    gram_sigmoid<<<dim3((NN + 63) / 64, (NN + 63) / 64), blk16>>>(out + EMB_OFF, out + READJ_OFF);

    // ---- decoder MLP ----
    sgemm_bias<<<dim3(NHID1 / 64, (NN + 63) / 64), blk16>>>(out + EMB_OFF, dw1, db1, p_d, NN, NHID2, NHID1);
    bn_stats<<<NHID1, 256>>>(p_d, NHID1);
    bn_apply_relu<<<(NN * NHID1 + 255) / 256, 256>>>(p_d, dbn_g, dbn_b, NHID1, NN * NHID1);
    sgemm_bias<<<dim3(NFEAT / 64, (NN + 63) / 64), blk16>>>(p_d, dw2, db2, out + REX_OFF, NN, NHID1, NFEAT);
}